// round 1
// baseline (speedup 1.0000x reference)
#include <cuda_runtime.h>
#include <cstdint>

#define L_LEN   65536
#define L_MASK  (L_LEN - 1)
#define CIN     8
#define COUT    8
#define FS      4
#define PP      8        // positions per thread
#define TPB     128

// ---- packed f32x2 helpers (Blackwell sm_100a+) ------------------------------
__device__ __forceinline__ float2 ffma2(float2 a, float2 b, float2 c) {
    float2 d;
    asm("fma.rn.f32x2 %0, %1, %2, %3;"
        : "=l"(reinterpret_cast<unsigned long long&>(d))
        : "l"(reinterpret_cast<const unsigned long long&>(a)),
          "l"(reinterpret_cast<const unsigned long long&>(b)),
          "l"(reinterpret_cast<const unsigned long long&>(c)));
    return d;
}

__device__ __forceinline__ float2 dup2(float x) {
    float2 d;
    asm("mov.b64 %0, {%1, %1};"
        : "=l"(reinterpret_cast<unsigned long long&>(d))
        : "f"(x));
    return d;
}

// ----------------------------------------------------------------------------
// out[b, co, l] = bias[co] + sum_{ci,k} x[b, ci, (l+k) mod L] * W[co, ci, k]
// Thread: one batch b, positions [l0, l0+8). Computes all 8 output channels,
// packed as 4 co-pairs in f32x2.
// ----------------------------------------------------------------------------
__global__ __launch_bounds__(TPB)
void conv_pbc_kernel(const float* __restrict__ x,
                     const float* __restrict__ W,
                     const float* __restrict__ bias,
                     float* __restrict__ out)
{
    // packed weights: w2s[ci][k][cp] = (W[2cp, ci, k], W[2cp+1, ci, k])
    __shared__ float2 w2s[CIN][FS][COUT / 2];
    __shared__ float2 b2s[COUT / 2];

    const int t = threadIdx.x;
    if (t < CIN * FS * (COUT / 2)) {         // 128 entries, one per thread
        const int cp = t & 3;
        const int k  = (t >> 2) & 3;
        const int ci = (t >> 4) & 7;
        const float lo = W[(2 * cp)     * CIN * FS + ci * FS + k];
        const float hi = W[(2 * cp + 1) * CIN * FS + ci * FS + k];
        w2s[ci][k][cp] = make_float2(lo, hi);
    }
    if (t < COUT / 2)
        b2s[t] = make_float2(bias[2 * t], bias[2 * t + 1]);
    __syncthreads();

    const int gtid = blockIdx.x * TPB + t;
    const int b    = gtid >> 13;             // 8192 threads per batch (L/PP)
    const int pidx = gtid & 8191;
    const int l0   = pidx * PP;

    const float* __restrict__ xb = x   + (size_t)b * CIN  * L_LEN;
    float*       __restrict__ ob = out + (size_t)b * COUT * L_LEN;

    // accumulators: acc[p][cp] = f32x2 over the co-pair, init = bias
    float2 acc[PP][4];
    {
        float2 b0 = b2s[0], b1 = b2s[1], b2 = b2s[2], b3 = b2s[3];
        #pragma unroll
        for (int p = 0; p < PP; ++p) {
            acc[p][0] = b0; acc[p][1] = b1; acc[p][2] = b2; acc[p][3] = b3;
        }
    }

    // fast path iff the 12-float window [l0, l0+12) stays in-bounds;
    // only the last thread per batch (l0 = 65528) wraps.
    const bool fast = (l0 + PP + FS <= L_LEN);

    #pragma unroll
    for (int ci = 0; ci < CIN; ++ci) {
        const float* __restrict__ xc = xb + (size_t)ci * L_LEN;

        float xv[12];
        if (fast) {
            const float4 a = *reinterpret_cast<const float4*>(xc + l0);
            const float4 bq = *reinterpret_cast<const float4*>(xc + l0 + 4);
            const float4 cq = *reinterpret_cast<const float4*>(xc + l0 + 8);
            xv[0] = a.x;  xv[1] = a.y;  xv[2] = a.z;  xv[3] = a.w;
            xv[4] = bq.x; xv[5] = bq.y; xv[6] = bq.z; xv[7] = bq.w;
            xv[8] = cq.x; xv[9] = cq.y; xv[10] = cq.z; xv[11] = cq.w;
        } else {
            #pragma unroll
            for (int i = 0; i < 12; ++i)
                xv[i] = xc[(l0 + i) & L_MASK];
        }

        // duplicate x into both f32x2 lanes (one MOV each)
        float2 xd[PP + FS - 1];
        #pragma unroll
        for (int i = 0; i < PP + FS - 1; ++i)
            xd[i] = dup2(xv[i]);

        // per-ci packed weights (broadcast LDS, conflict-free)
        float2 wv[FS][4];
        #pragma unroll
        for (int k = 0; k < FS; ++k)
            #pragma unroll
            for (int cp = 0; cp < 4; ++cp)
                wv[k][cp] = w2s[ci][k][cp];

        #pragma unroll
        for (int p = 0; p < PP; ++p) {
            #pragma unroll
            for (int k = 0; k < FS; ++k) {
                const float2 xk = xd[p + k];
                #pragma unroll
                for (int cp = 0; cp < 4; ++cp)
                    acc[p][cp] = ffma2(wv[k][cp], xk, acc[p][cp]);
            }
        }
    }

    // epilogue: transpose to per-channel float4 runs, vector stores
    #pragma unroll
    for (int cp = 0; cp < 4; ++cp) {
        float* __restrict__ o0 = ob + (size_t)(2 * cp)     * L_LEN + l0;
        float* __restrict__ o1 = ob + (size_t)(2 * cp + 1) * L_LEN + l0;

        float4 v;
        v.x = acc[0][cp].x; v.y = acc[1][cp].x; v.z = acc[2][cp].x; v.w = acc[3][cp].x;
        *reinterpret_cast<float4*>(o0) = v;
        v.x = acc[4][cp].x; v.y = acc[5][cp].x; v.z = acc[6][cp].x; v.w = acc[7][cp].x;
        *reinterpret_cast<float4*>(o0 + 4) = v;

        v.x = acc[0][cp].y; v.y = acc[1][cp].y; v.z = acc[2][cp].y; v.w = acc[3][cp].y;
        *reinterpret_cast<float4*>(o1) = v;
        v.x = acc[4][cp].y; v.y = acc[5][cp].y; v.z = acc[6][cp].y; v.w = acc[7][cp].y;
        *reinterpret_cast<float4*>(o1 + 4) = v;
    }
}

extern "C" void kernel_launch(void* const* d_in, const int* in_sizes, int n_in,
                              void* d_out, int out_size)
{
    const float* x    = (const float*)d_in[0];  // (64, 8, 65536)
    const float* W    = (const float*)d_in[1];  // (8, 8, 4)
    const float* bias = (const float*)d_in[2];  // (8,)
    float* out        = (float*)d_out;          // (64, 8, 65536)

    // total threads = 64 batches * (65536/8) = 524288 -> 4096 blocks of 128
    const int n_threads = 64 * (L_LEN / PP);
    const int n_blocks  = n_threads / TPB;
    conv_pbc_kernel<<<n_blocks, TPB>>>(x, W, bias, out);
}